// round 15
// baseline (speedup 1.0000x reference)
#include <cuda_runtime.h>
#include <cuda_bf16.h>
#include <cstdint>
#include <math.h>

// NT-Xent loss, GB300 (ptxas target sm_103 base: no tcgen05 -> mma.sync bf16).
// R14 = R13 with k_rows absorbed into k_tile's last CTA (completion counter):
//   k0: fp32 -> bf16 convert + zero rowsum + reset counter (at its ~6us floor).
//   k1: persistent single-barrier triangle mainloop (unchanged, wall-pinned);
//       after final flush, last CTA computes all row losses + mean -> out[0].
// Wrapped row-pair schedule, positives from bj-bi==64 tiles, C=130 shift
// (validated: exp args in [-400,-5], EX2 flushes deep-negatives to 0).

#define B_SZ 8192
#define N_SZ 16384
#define D_SZ 128
#define SHIFT_C 130.0f
#define K1C 2.8853900817779268f     //  2*log2(e)
#define K2C (-187.55035531556523f)  // -130*log2(e)

#define NB 128
#define NTRI 8256                   // 64 * 129
#define NCTA 296

__device__ __align__(16) __nv_bfloat16 g_zb[N_SZ * D_SZ];
__device__ float g_rowsum[N_SZ];
__device__ float g_pos[N_SZ];
__device__ int g_cnt;

// smem: A 32KB | B 2x32KB | red 4KB
#define SM_A 0
#define SM_B 32768
#define SM_RED 98304
#define SM_TOTAL 102400

__device__ __forceinline__ uint32_t swz(int row, int chunk) {
    return (uint32_t)(row * 256 + ((chunk ^ (row & 7)) * 16));
}
__device__ __forceinline__ uint32_t smem_u32(const void* p) {
    uint32_t a;
    asm("{ .reg .u64 t; cvta.to.shared.u64 t, %1; cvt.u32.u64 %0, t; }" : "=r"(a) : "l"(p));
    return a;
}
__device__ __forceinline__ float fast_ex2(float x) {
    float y; asm("ex2.approx.ftz.f32 %0, %1;" : "=f"(y) : "f"(x)); return y;
}
__device__ __forceinline__ void cp16(uint32_t dst, const void* src) {
    asm volatile("cp.async.cg.shared.global [%0], [%1], 16;" :: "r"(dst), "l"(src) : "memory");
}
#define CP_COMMIT() asm volatile("cp.async.commit_group;" ::: "memory")
#define CP_WAIT0()  asm volatile("cp.async.wait_group 0;" ::: "memory")

__device__ __forceinline__ void ldsm4(uint32_t a, uint32_t& r0, uint32_t& r1,
                                      uint32_t& r2, uint32_t& r3) {
    asm volatile("ldmatrix.sync.aligned.m8n8.x4.shared.b16 {%0,%1,%2,%3}, [%4];"
                 : "=r"(r0), "=r"(r1), "=r"(r2), "=r"(r3) : "r"(a));
}
__device__ __forceinline__ void mma16816(float* c, const uint32_t* a,
                                         uint32_t b0, uint32_t b1) {
    asm volatile(
        "mma.sync.aligned.m16n8k16.row.col.f32.bf16.bf16.f32 "
        "{%0,%1,%2,%3}, {%4,%5,%6,%7}, {%8,%9}, {%0,%1,%2,%3};"
        : "+f"(c[0]), "+f"(c[1]), "+f"(c[2]), "+f"(c[3])
        : "r"(a[0]), "r"(a[1]), "r"(a[2]), "r"(a[3]), "r"(b0), "r"(b1));
}

// wrapped row-pair decode: flat f in [0, 8256) -> (bi, bj), bi <= bj
__device__ __forceinline__ void decode_tri(int f, int& bi, int& bj) {
    int v = f / 129;
    int p = f - v * 129;
    if (p < 128 - v) { bi = v; bj = v + p; }
    else             { bi = 127 - v; bj = bi + (p - (128 - v)); }
}

// ======================= k0: fp32 -> bf16 + init =======================
__global__ __launch_bounds__(256)
void k_convert(const float* __restrict__ z1, const float* __restrict__ z2) {
    int t = blockIdx.x * 256 + threadIdx.x;          // 0..131071, 16 floats each
    if (t == 0) g_cnt = 0;
    if (t < N_SZ) g_rowsum[t] = 0.0f;
    const float* src = (t < 65536) ? (z1 + (size_t)t * 16)
                                   : (z2 + (size_t)(t - 65536) * 16);
    float4 a = *reinterpret_cast<const float4*>(src);
    float4 b = *reinterpret_cast<const float4*>(src + 4);
    float4 c = *reinterpret_cast<const float4*>(src + 8);
    float4 d = *reinterpret_cast<const float4*>(src + 12);
    uint4 o0, o1;
    {
        __nv_bfloat162 p0 = __float22bfloat162_rn(make_float2(a.x, a.y));
        __nv_bfloat162 p1 = __float22bfloat162_rn(make_float2(a.z, a.w));
        __nv_bfloat162 p2 = __float22bfloat162_rn(make_float2(b.x, b.y));
        __nv_bfloat162 p3 = __float22bfloat162_rn(make_float2(b.z, b.w));
        o0.x = *reinterpret_cast<uint32_t*>(&p0);
        o0.y = *reinterpret_cast<uint32_t*>(&p1);
        o0.z = *reinterpret_cast<uint32_t*>(&p2);
        o0.w = *reinterpret_cast<uint32_t*>(&p3);
    }
    {
        __nv_bfloat162 p0 = __float22bfloat162_rn(make_float2(c.x, c.y));
        __nv_bfloat162 p1 = __float22bfloat162_rn(make_float2(c.z, c.w));
        __nv_bfloat162 p2 = __float22bfloat162_rn(make_float2(d.x, d.y));
        __nv_bfloat162 p3 = __float22bfloat162_rn(make_float2(d.z, d.w));
        o1.x = *reinterpret_cast<uint32_t*>(&p0);
        o1.y = *reinterpret_cast<uint32_t*>(&p1);
        o1.z = *reinterpret_cast<uint32_t*>(&p2);
        o1.w = *reinterpret_cast<uint32_t*>(&p3);
    }
    uint4* dst = reinterpret_cast<uint4*>(reinterpret_cast<char*>(g_zb) + (size_t)t * 32);
    dst[0] = o0;
    dst[1] = o1;
}

// ======================= k1: persistent triangle tiles + tail reduce =======================
extern __shared__ __align__(1024) char smem[];

__device__ __forceinline__ void load_tile128(const char* zb, uint32_t dstBase,
                                             int blk, int tid) {
    int r = tid >> 1;
    int cb = (tid & 1) * 8;
    const char* src = zb + (size_t)(blk * 128 + r) * 256 + cb * 16;
#pragma unroll
    for (int c = 0; c < 8; c++)
        cp16(dstBase + swz(r, cb + c), src + c * 16);
}

// NOTE: caller must guarantee a __syncthreads since the last red[] use.
__device__ __forceinline__ void flush_rows(char* smemc, int bi, float s[8][2],
                                           int tid, int wid, int lane) {
    float* red = reinterpret_cast<float*>(smemc + SM_RED);
#pragma unroll
    for (int mt = 0; mt < 8; mt++)
#pragma unroll
        for (int h = 0; h < 2; h++) {
            float v = s[mt][h];
            v += __shfl_xor_sync(0xFFFFFFFFu, v, 1);
            v += __shfl_xor_sync(0xFFFFFFFFu, v, 2);
            if ((lane & 3) == 0)
                red[(mt * 16 + (lane >> 2) + h * 8) * 8 + wid] = v;
            s[mt][h] = 0.0f;
        }
    __syncthreads();
    if (tid < 128) {
        float a = 0.0f;
#pragma unroll
        for (int w = 0; w < 8; w++) a += red[tid * 8 + w];
        atomicAdd(&g_rowsum[bi * 128 + tid], a);
    }
}

__global__ __launch_bounds__(256, 2)
void k_tile(float* __restrict__ out) {
    const char* zb = reinterpret_cast<const char*>(g_zb);
    const uint32_t sb = smem_u32(smem);
    const int tid = threadIdx.x, wid = tid >> 5, lane = tid & 31;

    const int base = NTRI / NCTA;
    const int rem = NTRI - base * NCTA;
    const int bid = blockIdx.x;
    const int start = bid * base + (bid < rem ? bid : rem);
    const int n = base + (bid < rem ? 1 : 0);

    int bi, bj;
    decode_tri(start, bi, bj);

    load_tile128(zb, sb + SM_A, bi, tid);
    load_tile128(zb, sb + SM_B, bj, tid);
    CP_COMMIT();

    uint32_t aAddr[8];
#pragma unroll
    for (int mt = 0; mt < 8; mt++)
        aAddr[mt] = sb + SM_A + (uint32_t)((mt * 16 + (lane & 15)) * 256);
    const uint32_t bRowOff = (uint32_t)((wid * 16 + (lane & 15)) * 256);
    uint32_t offs[8];
#pragma unroll
    for (int ks = 0; ks < 8; ks++)
        offs[ks] = (((uint32_t)(ks * 2) + (uint32_t)(lane >> 4)) ^ (uint32_t)(lane & 7)) * 16;
    const int myRow0 = lane >> 2;
    const int myCol0 = wid * 16 + (lane & 3) * 2;

    float s[8][2];
#pragma unroll
    for (int i = 0; i < 8; i++) { s[i][0] = 0.0f; s[i][1] = 0.0f; }

    int bi_cur = bi;

    for (int i = 0; i < n; i++) {
        CP_WAIT0();
        __syncthreads();                       // publish B(i), retire buf[(i+1)&1]

        if (bi != bi_cur) {
            flush_rows(smem, bi_cur, s, tid, wid, lane);
            load_tile128(zb, sb + SM_A, bi, tid);
            CP_COMMIT();
            CP_WAIT0();
            __syncthreads();
            bi_cur = bi;
        }

        int nbi = bi, nbj = bj;
        if (i + 1 < n) {
            decode_tri(start + i + 1, nbi, nbj);
            load_tile128(zb, sb + SM_B + (uint32_t)((i + 1) & 1) * 32768, nbj, tid);
            CP_COMMIT();
        }

        const uint32_t bBase = sb + SM_B + (uint32_t)(i & 1) * 32768 + bRowOff;
        uint32_t bf[8][4];
#pragma unroll
        for (int ks = 0; ks < 8; ks++)
            ldsm4(bBase + offs[ks], bf[ks][0], bf[ks][1], bf[ks][2], bf[ks][3]);

        const bool offd = (bi != bj);
        const bool posT = (bj - bi == 64);
        float cs[4] = {0.0f, 0.0f, 0.0f, 0.0f};

#pragma unroll
        for (int mt = 0; mt < 8; mt++) {
            float acc[2][4];
#pragma unroll
            for (int nt = 0; nt < 2; nt++)
#pragma unroll
                for (int q = 0; q < 4; q++) acc[nt][q] = 0.0f;
#pragma unroll
            for (int ks = 0; ks < 8; ks++) {
                uint32_t a[4];
                ldsm4(aAddr[mt] + offs[ks], a[0], a[1], a[2], a[3]);
                mma16816(acc[0], a, bf[ks][0], bf[ks][2]);
                mma16816(acc[1], a, bf[ks][1], bf[ks][3]);
            }
            if (offd) {
#pragma unroll
                for (int nt = 0; nt < 2; nt++)
#pragma unroll
                    for (int q = 0; q < 4; q++) {
                        float e = fast_ex2(fmaf(acc[nt][q], K1C, K2C));
                        s[mt][q >> 1] += e;
                        cs[nt * 2 + (q & 1)] += e;
                    }
                if (posT) {
#pragma unroll
                    for (int nt = 0; nt < 2; nt++)
#pragma unroll
                        for (int q = 0; q < 4; q++) {
                            int r = myRow0 + mt * 16 + (q >> 1) * 8;
                            int c = myCol0 + nt * 8 + (q & 1);
                            if (r == c) {
                                float pv = 2.0f * acc[nt][q];
                                g_pos[bi * 128 + r] = pv;
                                g_pos[bi * 128 + r + B_SZ] = pv;
                            }
                        }
                }
            } else {
#pragma unroll
                for (int nt = 0; nt < 2; nt++)
#pragma unroll
                    for (int q = 0; q < 4; q++) {
                        int r = myRow0 + mt * 16 + (q >> 1) * 8;
                        int c = myCol0 + nt * 8 + (q & 1);
                        float e = fast_ex2(fmaf(acc[nt][q], K1C, K2C));
                        if (r == c) e = 0.0f;      // mask self-similarity
                        s[mt][q >> 1] += e;
                    }
            }
        }

        if (offd) {
#pragma unroll
            for (int c = 0; c < 4; c++) {
                float v = cs[c];
                v += __shfl_xor_sync(0xFFFFFFFFu, v, 4);
                v += __shfl_xor_sync(0xFFFFFFFFu, v, 8);
                v += __shfl_xor_sync(0xFFFFFFFFu, v, 16);
                if (lane < 4)
                    atomicAdd(&g_rowsum[bj * 128 + wid * 16 + lane * 2 + (c >> 1) * 8 + (c & 1)], v);
            }
        }

        bi = nbi; bj = nbj;
    }

    __syncthreads();                           // red[] reuse guard for final flush
    flush_rows(smem, bi_cur, s, tid, wid, lane);

    // ---- tail: last CTA computes row losses + mean -> out[0] ----
    __shared__ int sLast;
    __threadfence();
    __syncthreads();
    if (tid == 0) sLast = (atomicAdd(&g_cnt, 1) == NCTA - 1);
    __syncthreads();
    if (sLast) {
        __threadfence();
        float* red = reinterpret_cast<float*>(smem + SM_RED);
        float acc = 0.0f;
        for (int i = tid; i < N_SZ; i += 256)
            acc += -g_pos[i] + SHIFT_C + logf(g_rowsum[i]);
        red[tid] = acc;
        __syncthreads();
        for (int st = 128; st > 0; st >>= 1) {
            if (tid < st) red[tid] += red[tid + st];
            __syncthreads();
        }
        if (tid == 0) out[0] = red[0] * (1.0f / (float)N_SZ);
    }
}

// ======================= launch =======================
extern "C" void kernel_launch(void* const* d_in, const int* in_sizes, int n_in,
                              void* d_out, int out_size) {
    const float* z1 = (const float*)d_in[0];
    const float* z2 = (const float*)d_in[1];
    float* out = (float*)d_out;
    (void)in_sizes; (void)n_in; (void)out_size;

    cudaFuncSetAttribute(k_tile, cudaFuncAttributeMaxDynamicSharedMemorySize, SM_TOTAL);

    k_convert<<<512, 256>>>(z1, z2);
    k_tile<<<NCTA, 256, SM_TOTAL>>>(out);
}

// round 16
// speedup vs baseline: 1.1348x; 1.1348x over previous
#include <cuda_runtime.h>
#include <cuda_bf16.h>
#include <cstdint>
#include <math.h>

// NT-Xent loss, GB300 (ptxas target sm_103 base: no tcgen05 -> mma.sync bf16).
// R15: occupancy experiment -- 3 CTAs/SM (24 warps vs 16).
//   BN=64 col tiles (smem 66KB/CTA), warp grid 2x4 (warp = 64 rows x 16 cols).
//   Triangle over 128-row x 64-col tiles (16512), wrapped row-pair schedule
//   (virtual row v = real rows v & 127-v, 258 tiles each). Single-barrier
//   mainloop, A smem-resident per bi-run, B double-buffered cp.async.
//   Diagonal crossed by tiles bj64==2bi(+1): row-sums only, mask r==c.
//   Positives from tiles bj64-2bi in {128,129}. C=130 fixed shift.

#define B_SZ 8192
#define N_SZ 16384
#define D_SZ 128
#define SHIFT_C 130.0f
#define K1C 2.8853900817779268f     //  2*log2(e)
#define K2C (-187.55035531556523f)  // -130*log2(e)

#define NTILE 16512                 // 64 * 258
#define NCTA 444                    // 3 per SM

__device__ __align__(16) __nv_bfloat16 g_zb[N_SZ * D_SZ];
__device__ float g_rowsum[N_SZ];
__device__ float g_pos[N_SZ];
__device__ float g_blocksum[64];
__device__ int g_cnt;

// smem per CTA: A 32K | B 2x16K | red 2K  = 66K
#define SM_A 0
#define SM_B 32768
#define SM_RED 65536
#define SM_TOTAL 67584

__device__ __forceinline__ uint32_t swz(int row, int chunk) {
    return (uint32_t)(row * 256 + ((chunk ^ (row & 7)) * 16));
}
__device__ __forceinline__ uint32_t smem_u32(const void* p) {
    uint32_t a;
    asm("{ .reg .u64 t; cvta.to.shared.u64 t, %1; cvt.u32.u64 %0, t; }" : "=r"(a) : "l"(p));
    return a;
}
__device__ __forceinline__ float fast_ex2(float x) {
    float y; asm("ex2.approx.ftz.f32 %0, %1;" : "=f"(y) : "f"(x)); return y;
}
__device__ __forceinline__ void cp16(uint32_t dst, const void* src) {
    asm volatile("cp.async.cg.shared.global [%0], [%1], 16;" :: "r"(dst), "l"(src) : "memory");
}
#define CP_COMMIT() asm volatile("cp.async.commit_group;" ::: "memory")
#define CP_WAIT0()  asm volatile("cp.async.wait_group 0;" ::: "memory")

__device__ __forceinline__ void ldsm4(uint32_t a, uint32_t& r0, uint32_t& r1,
                                      uint32_t& r2, uint32_t& r3) {
    asm volatile("ldmatrix.sync.aligned.m8n8.x4.shared.b16 {%0,%1,%2,%3}, [%4];"
                 : "=r"(r0), "=r"(r1), "=r"(r2), "=r"(r3) : "r"(a));
}
__device__ __forceinline__ void mma16816(float* c, const uint32_t* a,
                                         uint32_t b0, uint32_t b1) {
    asm volatile(
        "mma.sync.aligned.m16n8k16.row.col.f32.bf16.bf16.f32 "
        "{%0,%1,%2,%3}, {%4,%5,%6,%7}, {%8,%9}, {%0,%1,%2,%3};"
        : "+f"(c[0]), "+f"(c[1]), "+f"(c[2]), "+f"(c[3])
        : "r"(a[0]), "r"(a[1]), "r"(a[2]), "r"(a[3]), "r"(b0), "r"(b1));
}

// wrapped row-pair decode: flat f in [0,16512) -> (bi in [0,128), bj64 in [0,256))
__device__ __forceinline__ void decode_tri(int f, int& bi, int& bj) {
    int v = f / 258;
    int p = f - v * 258;
    if (p < 256 - 2 * v) { bi = v; bj = 2 * v + p; }
    else                 { bi = 127 - v; bj = 2 * bi + (p - (256 - 2 * v)); }
}

// ======================= k0: fp32 -> bf16 + init =======================
__global__ __launch_bounds__(256)
void k_convert(const float* __restrict__ z1, const float* __restrict__ z2) {
    int t = blockIdx.x * 256 + threadIdx.x;          // 0..131071, 16 floats each
    if (t == 0) g_cnt = 0;
    if (t < N_SZ) g_rowsum[t] = 0.0f;
    const float* src = (t < 65536) ? (z1 + (size_t)t * 16)
                                   : (z2 + (size_t)(t - 65536) * 16);
    float4 a = *reinterpret_cast<const float4*>(src);
    float4 b = *reinterpret_cast<const float4*>(src + 4);
    float4 c = *reinterpret_cast<const float4*>(src + 8);
    float4 d = *reinterpret_cast<const float4*>(src + 12);
    uint4 o0, o1;
    {
        __nv_bfloat162 p0 = __float22bfloat162_rn(make_float2(a.x, a.y));
        __nv_bfloat162 p1 = __float22bfloat162_rn(make_float2(a.z, a.w));
        __nv_bfloat162 p2 = __float22bfloat162_rn(make_float2(b.x, b.y));
        __nv_bfloat162 p3 = __float22bfloat162_rn(make_float2(b.z, b.w));
        o0.x = *reinterpret_cast<uint32_t*>(&p0);
        o0.y = *reinterpret_cast<uint32_t*>(&p1);
        o0.z = *reinterpret_cast<uint32_t*>(&p2);
        o0.w = *reinterpret_cast<uint32_t*>(&p3);
    }
    {
        __nv_bfloat162 p0 = __float22bfloat162_rn(make_float2(c.x, c.y));
        __nv_bfloat162 p1 = __float22bfloat162_rn(make_float2(c.z, c.w));
        __nv_bfloat162 p2 = __float22bfloat162_rn(make_float2(d.x, d.y));
        __nv_bfloat162 p3 = __float22bfloat162_rn(make_float2(d.z, d.w));
        o1.x = *reinterpret_cast<uint32_t*>(&p0);
        o1.y = *reinterpret_cast<uint32_t*>(&p1);
        o1.z = *reinterpret_cast<uint32_t*>(&p2);
        o1.w = *reinterpret_cast<uint32_t*>(&p3);
    }
    uint4* dst = reinterpret_cast<uint4*>(reinterpret_cast<char*>(g_zb) + (size_t)t * 32);
    dst[0] = o0;
    dst[1] = o1;
}

// ======================= k1: persistent triangle tiles =======================
extern __shared__ __align__(1024) char smem[];

// A: 128 rows x 256B
__device__ __forceinline__ void load_tileA(const char* zb, uint32_t dstBase,
                                           int blk, int tid) {
    int r = tid >> 1;
    int cb = (tid & 1) * 8;
    const char* src = zb + (size_t)(blk * 128 + r) * 256 + cb * 16;
#pragma unroll
    for (int c = 0; c < 8; c++)
        cp16(dstBase + swz(r, cb + c), src + c * 16);
}
// B: 64 rows x 256B  (blk64 indexes 64-row blocks)
__device__ __forceinline__ void load_tileB(const char* zb, uint32_t dstBase,
                                           int blk64, int tid) {
    int r = tid >> 2;                  // 0..63
    int cb = (tid & 3) * 4;
    const char* src = zb + (size_t)(blk64 * 64 + r) * 256 + cb * 16;
#pragma unroll
    for (int c = 0; c < 4; c++)
        cp16(dstBase + swz(r, cb + c), src + c * 16);
}

// NOTE: caller must guarantee a __syncthreads since the last red[] use.
__device__ __forceinline__ void flush_rows(char* smemc, int bi, float s[4][2],
                                           int tid, int warp_m, int warp_n, int lane) {
    float* red = reinterpret_cast<float*>(smemc + SM_RED);   // [128][4]
#pragma unroll
    for (int mt = 0; mt < 4; mt++)
#pragma unroll
        for (int h = 0; h < 2; h++) {
            float v = s[mt][h];
            v += __shfl_xor_sync(0xFFFFFFFFu, v, 1);
            v += __shfl_xor_sync(0xFFFFFFFFu, v, 2);
            if ((lane & 3) == 0)
                red[(warp_m * 64 + mt * 16 + (lane >> 2) + h * 8) * 4 + warp_n] = v;
            s[mt][h] = 0.0f;
        }
    __syncthreads();
    if (tid < 128) {
        float a = red[tid * 4] + red[tid * 4 + 1] + red[tid * 4 + 2] + red[tid * 4 + 3];
        atomicAdd(&g_rowsum[bi * 128 + tid], a);
    }
}

__global__ __launch_bounds__(256, 3)
void k_tile() {
    const char* zb = reinterpret_cast<const char*>(g_zb);
    const uint32_t sb = smem_u32(smem);
    const int tid = threadIdx.x, wid = tid >> 5, lane = tid & 31;
    const int warp_m = wid >> 2, warp_n = wid & 3;   // 2 x 4

    const int base = NTILE / NCTA;                   // 37
    const int rem = NTILE - base * NCTA;             // 84
    const int bid = blockIdx.x;
    const int start = bid * base + (bid < rem ? bid : rem);
    const int n = base + (bid < rem ? 1 : 0);

    int bi, bj;
    decode_tri(start, bi, bj);

    load_tileA(zb, sb + SM_A, bi, tid);
    load_tileB(zb, sb + SM_B, bj, tid);
    CP_COMMIT();

    const uint32_t aBase = sb + SM_A +
        (uint32_t)((warp_m * 64 + (lane & 15)) * 256);
    const uint32_t bRowOff = (uint32_t)((warp_n * 16 + (lane & 15)) * 256);
    const uint32_t laneHi = (uint32_t)(lane >> 4);
    const uint32_t laneXor = (uint32_t)(lane & 7);
    const int myRow0 = warp_m * 64 + (lane >> 2);    // + mt*16 + 8h
    const int myColW = warp_n * 16 + (lane & 3) * 2; // + nt*8 + (q&1), within 64

    float s[4][2];
#pragma unroll
    for (int i = 0; i < 4; i++) { s[i][0] = 0.0f; s[i][1] = 0.0f; }

    int bi_cur = bi;

    for (int i = 0; i < n; i++) {
        CP_WAIT0();
        __syncthreads();                       // publish B(i), retire buf[(i+1)&1]

        if (bi != bi_cur) {
            flush_rows(smem, bi_cur, s, tid, warp_m, warp_n, lane);
            load_tileA(zb, sb + SM_A, bi, tid);
            CP_COMMIT();
            CP_WAIT0();
            __syncthreads();
            bi_cur = bi;
        }

        int nbi = bi, nbj = bj;
        if (i + 1 < n) {
            decode_tri(start + i + 1, nbi, nbj);
            load_tileB(zb, sb + SM_B + (uint32_t)((i + 1) & 1) * 16384, nbj, tid);
            CP_COMMIT();
        }

        // ---- preload B fragments (8 ks x 4 regs) ----
        const uint32_t bBase = sb + SM_B + (uint32_t)(i & 1) * 16384 + bRowOff;
        uint32_t bf[8][4];
#pragma unroll
        for (int ks = 0; ks < 8; ks++) {
            uint32_t off = (((uint32_t)(ks * 2) + laneHi) ^ laneXor) * 16;
            ldsm4(bBase + off, bf[ks][0], bf[ks][1], bf[ks][2], bf[ks][3]);
        }

        const int dRel = bj - 2 * bi;
        const bool diagT = (dRel == 0) | (dRel == 1);
        const bool posT = (dRel == 128) | (dRel == 129);
        float cs[4] = {0.0f, 0.0f, 0.0f, 0.0f};

        // ---- per-mt: MMA burst then immediate epilogue ----
#pragma unroll
        for (int mt = 0; mt < 4; mt++) {
            float acc[2][4];
#pragma unroll
            for (int nt = 0; nt < 2; nt++)
#pragma unroll
                for (int q = 0; q < 4; q++) acc[nt][q] = 0.0f;
#pragma unroll
            for (int ks = 0; ks < 8; ks++) {
                uint32_t off = (((uint32_t)(ks * 2) + laneHi) ^ laneXor) * 16;
                uint32_t a[4];
                ldsm4(aBase + (uint32_t)(mt * 16 * 256) + off, a[0], a[1], a[2], a[3]);
                mma16816(acc[0], a, bf[ks][0], bf[ks][2]);
                mma16816(acc[1], a, bf[ks][1], bf[ks][3]);
            }
            if (!diagT) {
#pragma unroll
                for (int nt = 0; nt < 2; nt++)
#pragma unroll
                    for (int q = 0; q < 4; q++) {
                        float e = fast_ex2(fmaf(acc[nt][q], K1C, K2C));
                        s[mt][q >> 1] += e;
                        cs[nt * 2 + (q & 1)] += e;
                    }
                if (posT) {
                    const int pOff = (dRel - 128) * 64;   // 0 or 64
#pragma unroll
                    for (int nt = 0; nt < 2; nt++)
#pragma unroll
                        for (int q = 0; q < 4; q++) {
                            int r = myRow0 + mt * 16 + (q >> 1) * 8;
                            int c = pOff + myColW + nt * 8 + (q & 1);
                            if (r == c) {
                                float pv = 2.0f * acc[nt][q];
                                g_pos[bi * 128 + r] = pv;
                                g_pos[bi * 128 + r + B_SZ] = pv;
                            }
                        }
                }
            } else {
                const int dOff = dRel * 64;               // 0 or 64
#pragma unroll
                for (int nt = 0; nt < 2; nt++)
#pragma unroll
                    for (int q = 0; q < 4; q++) {
                        int r = myRow0 + mt * 16 + (q >> 1) * 8;
                        int c = dOff + myColW + nt * 8 + (q & 1);
                        float e = fast_ex2(fmaf(acc[nt][q], K1C, K2C));
                        if (r == c) e = 0.0f;             // mask self-similarity
                        s[mt][q >> 1] += e;
                    }
            }
        }

        // ---- col sums -> rows bj*64 + warp cols (non-diag tiles) ----
        if (!diagT) {
#pragma unroll
            for (int c = 0; c < 4; c++) {
                float v = cs[c];
                v += __shfl_xor_sync(0xFFFFFFFFu, v, 4);
                v += __shfl_xor_sync(0xFFFFFFFFu, v, 8);
                v += __shfl_xor_sync(0xFFFFFFFFu, v, 16);
                if (lane < 4)
                    atomicAdd(&g_rowsum[bj * 64 + warp_n * 16 + lane * 2 +
                                        (c >> 1) * 8 + (c & 1)], v);
            }
        }

        bi = nbi; bj = nbj;
    }

    __syncthreads();                           // red[] reuse guard for final flush
    flush_rows(smem, bi_cur, s, tid, warp_m, warp_n, lane);
}

// ======================= k2: per-row loss + merged final mean =======================
__global__ __launch_bounds__(256)
void k_rows(float* __restrict__ out) {
    __shared__ float red[256];
    __shared__ int isLast;
    int i = blockIdx.x * 256 + threadIdx.x;
    float loss = -g_pos[i] + SHIFT_C + logf(g_rowsum[i]);
    red[threadIdx.x] = loss;
    __syncthreads();
    for (int st = 128; st > 0; st >>= 1) {
        if (threadIdx.x < st) red[threadIdx.x] += red[threadIdx.x + st];
        __syncthreads();
    }
    if (threadIdx.x == 0) {
        g_blocksum[blockIdx.x] = red[0];
        __threadfence();
        isLast = (atomicAdd(&g_cnt, 1) == 63);
    }
    __syncthreads();
    if (isLast) {
        float v = (threadIdx.x < 64) ? g_blocksum[threadIdx.x] : 0.0f;
        red[threadIdx.x] = v;
        __syncthreads();
        for (int st = 32; st > 0; st >>= 1) {
            if (threadIdx.x < st) red[threadIdx.x] += red[threadIdx.x + st];
            __syncthreads();
        }
        if (threadIdx.x == 0) out[0] = red[0] * (1.0f / (float)N_SZ);
    }
}

// ======================= launch =======================
extern "C" void kernel_launch(void* const* d_in, const int* in_sizes, int n_in,
                              void* d_out, int out_size) {
    const float* z1 = (const float*)d_in[0];
    const float* z2 = (const float*)d_in[1];
    float* out = (float*)d_out;
    (void)in_sizes; (void)n_in; (void)out_size;

    cudaFuncSetAttribute(k_tile, cudaFuncAttributeMaxDynamicSharedMemorySize, SM_TOTAL);

    k_convert<<<512, 256>>>(z1, z2);
    k_tile<<<NCTA, 256, SM_TOTAL>>>();
    k_rows<<<64, 256>>>(out);
}

// round 17
// speedup vs baseline: 1.1776x; 1.0377x over previous
#include <cuda_runtime.h>
#include <cuda_bf16.h>
#include <cstdint>
#include <math.h>

// NT-Xent loss, GB300 (ptxas target sm_103 base: no tcgen05 -> mma.sync bf16).
// R16: occupancy push to 32 warps/SM -- 512-thread CTAs, 2 CTAs/SM.
//   Same BN=64 tiling as R15 (per-tile overhead unchanged); warp grid 4x4
//   (warp = 32 rows x 16 cols). ks-outer MMA loop keeps live regs ~60
//   (acc 16 + transients) to fit the 64-reg cap at 1024 thr/SM.
//   Wrapped row-pair triangle schedule, single-barrier mainloop, A resident
//   per bi-run, B double-buffered cp.async, positives from dRel in {128,129},
//   diagonal masked in dRel in {0,1}. C=130 fixed shift.

#define B_SZ 8192
#define N_SZ 16384
#define D_SZ 128
#define SHIFT_C 130.0f
#define K1C 2.8853900817779268f     //  2*log2(e)
#define K2C (-187.55035531556523f)  // -130*log2(e)

#define NTILE 16512                 // 64 * 258 (128-row x 64-col tiles)
#define NCTA 296                    // 2 per SM

__device__ __align__(16) __nv_bfloat16 g_zb[N_SZ * D_SZ];
__device__ float g_rowsum[N_SZ];
__device__ float g_pos[N_SZ];
__device__ float g_blocksum[64];
__device__ int g_cnt;

// smem per CTA: A 32K | B 2x16K | red 2K = 66K  (2 CTAs = 132K <= 227K)
#define SM_A 0
#define SM_B 32768
#define SM_RED 65536
#define SM_TOTAL 67584

__device__ __forceinline__ uint32_t swz(int row, int chunk) {
    return (uint32_t)(row * 256 + ((chunk ^ (row & 7)) * 16));
}
__device__ __forceinline__ uint32_t smem_u32(const void* p) {
    uint32_t a;
    asm("{ .reg .u64 t; cvta.to.shared.u64 t, %1; cvt.u32.u64 %0, t; }" : "=r"(a) : "l"(p));
    return a;
}
__device__ __forceinline__ float fast_ex2(float x) {
    float y; asm("ex2.approx.ftz.f32 %0, %1;" : "=f"(y) : "f"(x)); return y;
}
__device__ __forceinline__ void cp16(uint32_t dst, const void* src) {
    asm volatile("cp.async.cg.shared.global [%0], [%1], 16;" :: "r"(dst), "l"(src) : "memory");
}
#define CP_COMMIT() asm volatile("cp.async.commit_group;" ::: "memory")
#define CP_WAIT0()  asm volatile("cp.async.wait_group 0;" ::: "memory")

__device__ __forceinline__ void ldsm4(uint32_t a, uint32_t& r0, uint32_t& r1,
                                      uint32_t& r2, uint32_t& r3) {
    asm volatile("ldmatrix.sync.aligned.m8n8.x4.shared.b16 {%0,%1,%2,%3}, [%4];"
                 : "=r"(r0), "=r"(r1), "=r"(r2), "=r"(r3) : "r"(a));
}
__device__ __forceinline__ void mma16816(float* c, const uint32_t* a,
                                         uint32_t b0, uint32_t b1) {
    asm volatile(
        "mma.sync.aligned.m16n8k16.row.col.f32.bf16.bf16.f32 "
        "{%0,%1,%2,%3}, {%4,%5,%6,%7}, {%8,%9}, {%0,%1,%2,%3};"
        : "+f"(c[0]), "+f"(c[1]), "+f"(c[2]), "+f"(c[3])
        : "r"(a[0]), "r"(a[1]), "r"(a[2]), "r"(a[3]), "r"(b0), "r"(b1));
}

// wrapped row-pair decode: flat f in [0,16512) -> (bi in [0,128), bj64 in [0,256))
__device__ __forceinline__ void decode_tri(int f, int& bi, int& bj) {
    int v = f / 258;
    int p = f - v * 258;
    if (p < 256 - 2 * v) { bi = v; bj = 2 * v + p; }
    else                 { bi = 127 - v; bj = 2 * bi + (p - (256 - 2 * v)); }
}

// ======================= k0: fp32 -> bf16 + init =======================
__global__ __launch_bounds__(256)
void k_convert(const float* __restrict__ z1, const float* __restrict__ z2) {
    int t = blockIdx.x * 256 + threadIdx.x;          // 0..131071, 16 floats each
    if (t == 0) g_cnt = 0;
    if (t < N_SZ) g_rowsum[t] = 0.0f;
    const float* src = (t < 65536) ? (z1 + (size_t)t * 16)
                                   : (z2 + (size_t)(t - 65536) * 16);
    float4 a = *reinterpret_cast<const float4*>(src);
    float4 b = *reinterpret_cast<const float4*>(src + 4);
    float4 c = *reinterpret_cast<const float4*>(src + 8);
    float4 d = *reinterpret_cast<const float4*>(src + 12);
    uint4 o0, o1;
    {
        __nv_bfloat162 p0 = __float22bfloat162_rn(make_float2(a.x, a.y));
        __nv_bfloat162 p1 = __float22bfloat162_rn(make_float2(a.z, a.w));
        __nv_bfloat162 p2 = __float22bfloat162_rn(make_float2(b.x, b.y));
        __nv_bfloat162 p3 = __float22bfloat162_rn(make_float2(b.z, b.w));
        o0.x = *reinterpret_cast<uint32_t*>(&p0);
        o0.y = *reinterpret_cast<uint32_t*>(&p1);
        o0.z = *reinterpret_cast<uint32_t*>(&p2);
        o0.w = *reinterpret_cast<uint32_t*>(&p3);
    }
    {
        __nv_bfloat162 p0 = __float22bfloat162_rn(make_float2(c.x, c.y));
        __nv_bfloat162 p1 = __float22bfloat162_rn(make_float2(c.z, c.w));
        __nv_bfloat162 p2 = __float22bfloat162_rn(make_float2(d.x, d.y));
        __nv_bfloat162 p3 = __float22bfloat162_rn(make_float2(d.z, d.w));
        o1.x = *reinterpret_cast<uint32_t*>(&p0);
        o1.y = *reinterpret_cast<uint32_t*>(&p1);
        o1.z = *reinterpret_cast<uint32_t*>(&p2);
        o1.w = *reinterpret_cast<uint32_t*>(&p3);
    }
    uint4* dst = reinterpret_cast<uint4*>(reinterpret_cast<char*>(g_zb) + (size_t)t * 32);
    dst[0] = o0;
    dst[1] = o1;
}

// ======================= k1: persistent triangle tiles =======================
extern __shared__ __align__(1024) char smem[];

// A: 128 rows x 256B, 512 threads -> 4 chunks each
__device__ __forceinline__ void load_tileA(const char* zb, uint32_t dstBase,
                                           int blk, int tid) {
    int r = tid >> 2;                  // 0..127
    int cb = (tid & 3) * 4;
    const char* src = zb + (size_t)(blk * 128 + r) * 256 + cb * 16;
#pragma unroll
    for (int c = 0; c < 4; c++)
        cp16(dstBase + swz(r, cb + c), src + c * 16);
}
// B: 64 rows x 256B, 512 threads -> 2 chunks each
__device__ __forceinline__ void load_tileB(const char* zb, uint32_t dstBase,
                                           int blk64, int tid) {
    int r = tid >> 3;                  // 0..63
    int cb = (tid & 7) * 2;
    const char* src = zb + (size_t)(blk64 * 64 + r) * 256 + cb * 16;
#pragma unroll
    for (int c = 0; c < 2; c++)
        cp16(dstBase + swz(r, cb + c), src + c * 16);
}

// NOTE: caller must guarantee a __syncthreads since the last red[] use.
__device__ __forceinline__ void flush_rows(char* smemc, int bi, float s[2][2],
                                           int tid, int warp_m, int warp_n, int lane) {
    float* red = reinterpret_cast<float*>(smemc + SM_RED);   // [128][4]
#pragma unroll
    for (int mt = 0; mt < 2; mt++)
#pragma unroll
        for (int h = 0; h < 2; h++) {
            float v = s[mt][h];
            v += __shfl_xor_sync(0xFFFFFFFFu, v, 1);
            v += __shfl_xor_sync(0xFFFFFFFFu, v, 2);
            if ((lane & 3) == 0)
                red[(warp_m * 32 + mt * 16 + (lane >> 2) + h * 8) * 4 + warp_n] = v;
            s[mt][h] = 0.0f;
        }
    __syncthreads();
    if (tid < 128) {
        float a = red[tid * 4] + red[tid * 4 + 1] + red[tid * 4 + 2] + red[tid * 4 + 3];
        atomicAdd(&g_rowsum[bi * 128 + tid], a);
    }
}

__global__ __launch_bounds__(512, 2)
void k_tile() {
    const char* zb = reinterpret_cast<const char*>(g_zb);
    const uint32_t sb = smem_u32(smem);
    const int tid = threadIdx.x, wid = tid >> 5, lane = tid & 31;
    const int warp_m = wid >> 2, warp_n = wid & 3;   // 4 x 4

    const int base = NTILE / NCTA;                   // 55
    const int rem = NTILE - base * NCTA;             // 232
    const int bid = blockIdx.x;
    const int start = bid * base + (bid < rem ? bid : rem);
    const int n = base + (bid < rem ? 1 : 0);

    int bi, bj;
    decode_tri(start, bi, bj);

    load_tileA(zb, sb + SM_A, bi, tid);
    load_tileB(zb, sb + SM_B, bj, tid);
    CP_COMMIT();

    const uint32_t aBase = sb + SM_A +
        (uint32_t)((warp_m * 32 + (lane & 15)) * 256);
    const uint32_t bRowOff = (uint32_t)((warp_n * 16 + (lane & 15)) * 256);
    const uint32_t laneHi = (uint32_t)(lane >> 4);
    const uint32_t laneXor = (uint32_t)(lane & 7);
    const int myRow0 = warp_m * 32 + (lane >> 2);    // + mt*16 + 8h
    const int myColW = warp_n * 16 + (lane & 3) * 2; // + nt*8 + (q&1), within 64

    float s[2][2];
    s[0][0] = s[0][1] = s[1][0] = s[1][1] = 0.0f;

    int bi_cur = bi;

    for (int i = 0; i < n; i++) {
        CP_WAIT0();
        __syncthreads();                       // publish B(i), retire buf[(i+1)&1]

        if (bi != bi_cur) {
            flush_rows(smem, bi_cur, s, tid, warp_m, warp_n, lane);
            load_tileA(zb, sb + SM_A, bi, tid);
            CP_COMMIT();
            CP_WAIT0();
            __syncthreads();
            bi_cur = bi;
        }

        int nbi = bi, nbj = bj;
        if (i + 1 < n) {
            decode_tri(start + i + 1, nbi, nbj);
            load_tileB(zb, sb + SM_B + (uint32_t)((i + 1) & 1) * 16384, nbj, tid);
            CP_COMMIT();
        }

        // ---- ks-outer MMA loop: acc 16 live regs, transients only ----
        const uint32_t bBase = sb + SM_B + (uint32_t)(i & 1) * 16384 + bRowOff;
        float acc[2][2][4];
#pragma unroll
        for (int mt = 0; mt < 2; mt++)
#pragma unroll
            for (int nt = 0; nt < 2; nt++)
#pragma unroll
                for (int q = 0; q < 4; q++) acc[mt][nt][q] = 0.0f;

#pragma unroll
        for (int ks = 0; ks < 8; ks++) {
            uint32_t off = (((uint32_t)(ks * 2) + laneHi) ^ laneXor) * 16;
            uint32_t b0, b1, b2, b3;
            ldsm4(bBase + off, b0, b1, b2, b3);
#pragma unroll
            for (int mt = 0; mt < 2; mt++) {
                uint32_t a[4];
                ldsm4(aBase + (uint32_t)(mt * 16 * 256) + off, a[0], a[1], a[2], a[3]);
                mma16816(acc[mt][0], a, b0, b2);
                mma16816(acc[mt][1], a, b1, b3);
            }
        }

        const int dRel = bj - 2 * bi;
        const bool diagT = (dRel == 0) | (dRel == 1);
        const bool posT = (dRel == 128) | (dRel == 129);
        float cs[4] = {0.0f, 0.0f, 0.0f, 0.0f};

        if (!diagT) {
#pragma unroll
            for (int mt = 0; mt < 2; mt++)
#pragma unroll
                for (int nt = 0; nt < 2; nt++)
#pragma unroll
                    for (int q = 0; q < 4; q++) {
                        float e = fast_ex2(fmaf(acc[mt][nt][q], K1C, K2C));
                        s[mt][q >> 1] += e;
                        cs[nt * 2 + (q & 1)] += e;
                    }
            if (posT) {
                const int pOff = (dRel - 128) * 64;   // 0 or 64
#pragma unroll
                for (int mt = 0; mt < 2; mt++)
#pragma unroll
                    for (int nt = 0; nt < 2; nt++)
#pragma unroll
                        for (int q = 0; q < 4; q++) {
                            int r = myRow0 + mt * 16 + (q >> 1) * 8;
                            int c = pOff + myColW + nt * 8 + (q & 1);
                            if (r == c) {
                                float pv = 2.0f * acc[mt][nt][q];
                                g_pos[bi * 128 + r] = pv;
                                g_pos[bi * 128 + r + B_SZ] = pv;
                            }
                        }
            }
            // col sums -> rows bj*64 + warp cols
#pragma unroll
            for (int c = 0; c < 4; c++) {
                float v = cs[c];
                v += __shfl_xor_sync(0xFFFFFFFFu, v, 4);
                v += __shfl_xor_sync(0xFFFFFFFFu, v, 8);
                v += __shfl_xor_sync(0xFFFFFFFFu, v, 16);
                if (lane < 4)
                    atomicAdd(&g_rowsum[bj * 64 + warp_n * 16 + lane * 2 +
                                        (c >> 1) * 8 + (c & 1)], v);
            }
        } else {
            const int dOff = dRel * 64;               // 0 or 64
#pragma unroll
            for (int mt = 0; mt < 2; mt++)
#pragma unroll
                for (int nt = 0; nt < 2; nt++)
#pragma unroll
                    for (int q = 0; q < 4; q++) {
                        int r = myRow0 + mt * 16 + (q >> 1) * 8;
                        int c = dOff + myColW + nt * 8 + (q & 1);
                        float e = fast_ex2(fmaf(acc[mt][nt][q], K1C, K2C));
                        if (r == c) e = 0.0f;         // mask self-similarity
                        s[mt][q >> 1] += e;
                    }
        }

        bi = nbi; bj = nbj;
    }

    __syncthreads();                           // red[] reuse guard for final flush
    flush_rows(smem, bi_cur, s, tid, warp_m, warp_n, lane);
}

// ======================= k2: per-row loss + merged final mean =======================
__global__ __launch_bounds__(256)
void k_rows(float* __restrict__ out) {
    __shared__ float red[256];
    __shared__ int isLast;
    int i = blockIdx.x * 256 + threadIdx.x;
    float loss = -g_pos[i] + SHIFT_C + logf(g_rowsum[i]);
    red[threadIdx.x] = loss;
    __syncthreads();
    for (int st = 128; st > 0; st >>= 1) {
        if (threadIdx.x < st) red[threadIdx.x] += red[threadIdx.x + st];
        __syncthreads();
    }
    if (threadIdx.x == 0) {
        g_blocksum[blockIdx.x] = red[0];
        __threadfence();
        isLast = (atomicAdd(&g_cnt, 1) == 63);
    }
    __syncthreads();
    if (isLast) {
        float v = (threadIdx.x < 64) ? g_blocksum[threadIdx.x] : 0.0f;
        red[threadIdx.x] = v;
        __syncthreads();
        for (int st = 32; st > 0; st >>= 1) {
            if (threadIdx.x < st) red[threadIdx.x] += red[threadIdx.x + st];
            __syncthreads();
        }
        if (threadIdx.x == 0) out[0] = red[0] * (1.0f / (float)N_SZ);
    }
}

// ======================= launch =======================
extern "C" void kernel_launch(void* const* d_in, const int* in_sizes, int n_in,
                              void* d_out, int out_size) {
    const float* z1 = (const float*)d_in[0];
    const float* z2 = (const float*)d_in[1];
    float* out = (float*)d_out;
    (void)in_sizes; (void)n_in; (void)out_size;

    cudaFuncSetAttribute(k_tile, cudaFuncAttributeMaxDynamicSharedMemorySize, SM_TOTAL);

    k_convert<<<512, 256>>>(z1, z2);
    k_tile<<<NCTA, 512, SM_TOTAL>>>();
    k_rows<<<64, 256>>>(out);
}